// round 2
// baseline (speedup 1.0000x reference)
#include <cuda_runtime.h>
#include <cstdint>

// Problem constants (fixed shapes per reference setup_inputs)
#define CIN   64
#define COUT  64
#define HH    256
#define WW    256
#define BATCH 16

// Tile config
#define TW  32   // output tile width per block
#define TH  8    // output tile height per block
#define TCO 32   // cout per block
#define CC  8    // cin chunk staged in smem
#define XP  35   // x smem row pitch (35 mod 32 = 3 -> conflict-free for (3*ty+8*tx+i))

// Scratch: quantized+duplicated weights, folded BN params
__device__ float d_Wq[CIN * 9 * COUT * 2];   // [ci][r][co][2] (dup f32x2 pairs)
__device__ float d_g[COUT];
__device__ float d_bias[COUT];

// ---------------- packed f32x2 helpers (ptxas won't emit these from C++) -----
__device__ __forceinline__ unsigned long long pack2(float lo, float hi) {
    unsigned long long r;
    asm("mov.b64 %0, {%1, %2};" : "=l"(r) : "f"(lo), "f"(hi));
    return r;
}
__device__ __forceinline__ void fma2(unsigned long long& d,
                                     unsigned long long a, unsigned long long b) {
    asm("fma.rn.f32x2 %0, %1, %2, %0;" : "+l"(d) : "l"(a), "l"(b));
}
__device__ __forceinline__ void add2(unsigned long long& d, unsigned long long a) {
    asm("add.rn.f32x2 %0, %1, %0;" : "+l"(d) : "l"(a));
}
__device__ __forceinline__ float2 unpack2(unsigned long long v) {
    float2 f;
    asm("mov.b64 {%0, %1}, %2;" : "=f"(f.x), "=f"(f.y) : "l"(v));
    return f;
}

// ---------------- prep: int4 fake-quant weights + BN fold -------------------
__global__ void prep_kernel(const float* __restrict__ W,
                            const float* __restrict__ gamma,
                            const float* __restrict__ beta,
                            const float* __restrict__ mean,
                            const float* __restrict__ var) {
    int co = blockIdx.x;               // one block per output channel
    __shared__ float red[256];
    float m = 0.f;
    for (int i = threadIdx.x; i < CIN * 9; i += blockDim.x)
        m = fmaxf(m, fabsf(W[co * CIN * 9 + i]));
    red[threadIdx.x] = m;
    __syncthreads();
    for (int s = 128; s > 0; s >>= 1) {
        if (threadIdx.x < s)
            red[threadIdx.x] = fmaxf(red[threadIdx.x], red[threadIdx.x + s]);
        __syncthreads();
    }
    float scale = fmaxf(red[0] / 7.0f, 1e-8f);

    for (int i = threadIdx.x; i < CIN * 9; i += blockDim.x) {
        int ci = i / 9, r = i - ci * 9;
        float w = W[co * CIN * 9 + i];
        float q = rintf(w / scale);                 // round-half-even = jnp.round
        q = fminf(fmaxf(q, -7.f), 7.f) * scale;
        int dst = ((ci * 9 + r) * COUT + co) * 2;   // duplicated pair
        d_Wq[dst]     = q;
        d_Wq[dst + 1] = q;
    }
    if (threadIdx.x == 0) {
        float g = gamma[co] / sqrtf(var[co] + 1e-5f);
        d_g[co]    = g;
        d_bias[co] = beta[co] - mean[co] * g;
    }
}

// ---------------- main fused conv+BN+QuantReLU ------------------------------
__global__ __launch_bounds__(256, 2)
void conv_kernel(const float* __restrict__ x,
                 const float* __restrict__ act_scale,
                 float* __restrict__ out) {
    __shared__ __align__(16) float xs[CC][TH + 2][XP];
    __shared__ __align__(16) float ws[CC][9][TCO * 2];   // dup f32x2 pairs

    const int tid = threadIdx.x;
    const int tx = tid & 3;          // w-octet: pixels tx*8 .. tx*8+7
    const int ty = (tid >> 2) & 7;   // output row within tile
    const int tz = tid >> 5;         // cout quad (== warp id)

    const int w0 = blockIdx.x * TW;
    const int h0 = blockIdx.y * TH;
    const int b  = blockIdx.z >> 1;
    const int cb = (blockIdx.z & 1) * TCO;

    const float* xb = x + (size_t)b * CIN * HH * WW;
    const float2* wsrc = (const float2*)d_Wq;

    unsigned long long macc[4][4];   // master acc: [co][pixel-pair], f32x2
    #pragma unroll
    for (int a = 0; a < 4; a++)
        #pragma unroll
        for (int j = 0; j < 4; j++) macc[a][j] = 0ull;

    for (int c0 = 0; c0 < CIN; c0 += CC) {
        // ---- stage x tile (with halo, zero-padded at borders) ----
        #pragma unroll 1
        for (int i = tid; i < CC * (TH + 2) * 34; i += 256) {
            int ci  = i / ((TH + 2) * 34);
            int rem = i - ci * ((TH + 2) * 34);
            int hl  = rem / 34;
            int wl  = rem - hl * 34;
            int gh = h0 - 1 + hl;
            int gw = w0 - 1 + wl;
            float v = 0.f;
            if ((unsigned)gh < HH && (unsigned)gw < WW)
                v = xb[(size_t)(c0 + ci) * (HH * WW) + gh * WW + gw];
            xs[ci][hl][wl] = v;
        }
        // ---- stage duplicated weights for this chunk ----
        {
            float2* wsd = (float2*)ws;
            #pragma unroll 1
            for (int i = tid; i < CC * 9 * TCO; i += 256) {
                int ci  = i / (9 * TCO);
                int rem = i - ci * 9 * TCO;
                int r   = rem >> 5;
                int co  = rem & 31;
                wsd[(ci * 9 + r) * TCO + co] =
                    wsrc[((c0 + ci) * 9 + r) * COUT + cb + co];
            }
        }
        __syncthreads();

        // per-chunk partial accumulators (shorter fp32 chains -> less
        // summation noise; quant snapping amplifies ordering noise)
        unsigned long long cacc[4][4];
        #pragma unroll
        for (int a = 0; a < 4; a++)
            #pragma unroll
            for (int j = 0; j < 4; j++) cacc[a][j] = 0ull;

        #pragma unroll 2
        for (int ci = 0; ci < CC; ci++) {
            #pragma unroll
            for (int kh = 0; kh < 3; kh++) {
                float xr[10];
                #pragma unroll
                for (int i = 0; i < 10; i++)
                    xr[i] = xs[ci][ty + kh][tx * 8 + i];
                unsigned long long p[3][4];
                #pragma unroll
                for (int j = 0; j < 4; j++) {
                    p[0][j] = pack2(xr[2 * j],     xr[2 * j + 1]);
                    p[1][j] = pack2(xr[2 * j + 1], xr[2 * j + 2]);
                    p[2][j] = pack2(xr[2 * j + 2], xr[2 * j + 3]);
                }
                #pragma unroll
                for (int kw = 0; kw < 3; kw++) {
                    const unsigned long long* wp =
                        (const unsigned long long*)&ws[ci][kh * 3 + kw][0];
                    unsigned long long wv[4];
                    #pragma unroll
                    for (int co = 0; co < 4; co++) wv[co] = wp[tz * 4 + co];
                    #pragma unroll
                    for (int co = 0; co < 4; co++)
                        #pragma unroll
                        for (int j = 0; j < 4; j++)
                            fma2(cacc[co][j], p[kw][j], wv[co]);
                }
            }
        }
        #pragma unroll
        for (int a = 0; a < 4; a++)
            #pragma unroll
            for (int j = 0; j < 4; j++) add2(macc[a][j], cacc[a][j]);
        __syncthreads();
    }

    // ---- epilogue: BN (folded) + ReLU + uint4 fake-quant ----
    const float s = fmaxf(act_scale[0], 1e-8f);
    const int h = h0 + ty;
    const int wbase = w0 + tx * 8;
    #pragma unroll
    for (int co = 0; co < 4; co++) {
        const int c = cb + tz * 4 + co;
        const float g  = d_g[c];
        const float bi = d_bias[c];
        float* op = out + (((size_t)b * COUT + c) * HH + h) * WW + wbase;
        #pragma unroll
        for (int j = 0; j < 4; j++) {
            float2 v = unpack2(macc[co][j]);
            float y0 = fmaxf(fmaf(v.x, g, bi), 0.f);
            float y1 = fmaxf(fmaf(v.y, g, bi), 0.f);
            float q0 = fminf(rintf(y0 / s), 15.f);   // IEEE div + half-even
            float q1 = fminf(rintf(y1 / s), 15.f);
            float2 o;
            o.x = q0 * s;
            o.y = q1 * s;
            *(float2*)(op + 2 * j) = o;
        }
    }
}

// ---------------- harness entry ---------------------------------------------
extern "C" void kernel_launch(void* const* d_in, const int* in_sizes, int n_in,
                              void* d_out, int out_size) {
    const float* x     = (const float*)d_in[0];
    const float* W     = (const float*)d_in[1];
    const float* gamma = (const float*)d_in[2];
    const float* beta  = (const float*)d_in[3];
    const float* mean  = (const float*)d_in[4];
    const float* var   = (const float*)d_in[5];
    const float* act   = (const float*)d_in[6];
    float* out = (float*)d_out;
    (void)in_sizes; (void)n_in; (void)out_size;

    prep_kernel<<<COUT, 256>>>(W, gamma, beta, mean, var);
    dim3 grid(WW / TW, HH / TH, BATCH * 2);
    conv_kernel<<<grid, 256>>>(x, act, out);
}